// round 17
// baseline (speedup 1.0000x reference)
#include <cuda_runtime.h>
#include <cuda_bf16.h>

// BasicLS: per-batch least squares.
// For each b: A = [-x[:,1:4], 1]  (32x4), r = x[:,0].
// out[b] = (A^T A)^{-1} A^T r   (4 floats), via normal equations + Cholesky.
//
// R15 champion structure + Blackwell 256-bit loads:
//   - 4 threads per batch, 8 batches per warp (proven best reduce/solve cost).
//   - Each thread issues 4 front-batched LDG.E.256 (ld.global.nc.v8.f32),
//     each covering TWO consecutive rows (32 B). The 4-lane group therefore
//     covers one FULL 128-byte L2 line per instruction (no split-sector
//     fills), at half the instruction / L1tex-wavefront count of the float4
//     version, with identical compute structure.
//   - Reverse-order consumption defeats load-sinking; __launch_bounds__(256,4)
//     keeps the 64-reg budget that lets all 4 loads stay live.
//   - 2-step shfl_xor reduction; lane sub==0 does rsqrt-form Cholesky.

__device__ __forceinline__ void ldg256(const float* __restrict__ p, float* v)
{
    asm volatile("ld.global.nc.v8.f32 {%0,%1,%2,%3,%4,%5,%6,%7}, [%8];"
                 : "=f"(v[0]), "=f"(v[1]), "=f"(v[2]), "=f"(v[3]),
                   "=f"(v[4]), "=f"(v[5]), "=f"(v[6]), "=f"(v[7])
                 : "l"(p));
}

__global__ __launch_bounds__(256, 4)
void basic_ls_kernel(const float* __restrict__ x,
                     float4* __restrict__ out)
{
    const int tid   = blockIdx.x * blockDim.x + threadIdx.x;
    const int warp  = tid >> 5;
    const int lane  = tid & 31;
    const int group = lane >> 2;   // batch within warp (0..7)
    const int sub   = lane & 3;    // row-pair slot within batch (0..3)
    const int batch = warp * 8 + group;

    // Thread handles rows {k*8 + 2*sub, k*8 + 2*sub + 1}, k = 0..3.
    const float* __restrict__ base = x + (size_t)batch * 128 + sub * 8;

    // ---- Front-batched loads: 4 independent LDG.E.256 before ANY math.
    //      Each instruction: 4 lanes x 32 B = one full 128-B line. ----
    float v[4][8];
#pragma unroll
    for (int k = 0; k < 4; ++k)
        ldg256(base + k * 32, v[k]);

    // ---- Accumulate normal-equation sums (reverse order). ----
    float sx1 = 0.f, sx2 = 0.f, sx3 = 0.f, sr = 0.f;
    float s11 = 0.f, s12 = 0.f, s13 = 0.f;
    float s22 = 0.f, s23 = 0.f, s33 = 0.f;
    float t1  = 0.f, t2  = 0.f, t3  = 0.f;

#pragma unroll
    for (int k = 3; k >= 0; --k) {
#pragma unroll
        for (int h = 0; h < 2; ++h) {
            const float r = v[k][4 * h + 0];
            const float a = v[k][4 * h + 1];
            const float b = v[k][4 * h + 2];
            const float c = v[k][4 * h + 3];
            sx1 += a;  sx2 += b;  sx3 += c;  sr += r;
            s11 = fmaf(a, a, s11);
            s12 = fmaf(a, b, s12);
            s13 = fmaf(a, c, s13);
            s22 = fmaf(b, b, s22);
            s23 = fmaf(b, c, s23);
            s33 = fmaf(c, c, s33);
            t1  = fmaf(a, r, t1);
            t2  = fmaf(b, r, t2);
            t3  = fmaf(c, r, t3);
        }
    }

    // ---- Reduce the 13 sums across the 4-lane group (xor 1, then 2). ----
#pragma unroll
    for (int off = 1; off <= 2; off <<= 1) {
        sx1 += __shfl_xor_sync(0xffffffffu, sx1, off);
        sx2 += __shfl_xor_sync(0xffffffffu, sx2, off);
        sx3 += __shfl_xor_sync(0xffffffffu, sx3, off);
        sr  += __shfl_xor_sync(0xffffffffu, sr,  off);
        s11 += __shfl_xor_sync(0xffffffffu, s11, off);
        s12 += __shfl_xor_sync(0xffffffffu, s12, off);
        s13 += __shfl_xor_sync(0xffffffffu, s13, off);
        s22 += __shfl_xor_sync(0xffffffffu, s22, off);
        s23 += __shfl_xor_sync(0xffffffffu, s23, off);
        s33 += __shfl_xor_sync(0xffffffffu, s33, off);
        t1  += __shfl_xor_sync(0xffffffffu, t1,  off);
        t2  += __shfl_xor_sync(0xffffffffu, t2,  off);
        t3  += __shfl_xor_sync(0xffffffffu, t3,  off);
    }

    if (sub == 0) {
        // Normal equations with A = [-x1, -x2, -x3, 1]:
        const float g11 = s11, g12 = s12, g13 = s13, g14 = -sx1;
        const float g22 = s22, g23 = s23, g24 = -sx2;
        const float g33 = s33, g34 = -sx3;
        const float g44 = 32.0f;               // M rows, a4 == 1, no padding
        const float b1 = -t1, b2 = -t2, b3 = -t3, b4 = sr;

        // Cholesky in rsqrt form.
        const float i11 = rsqrtf(g11);
        const float l21 = g12 * i11;
        const float l31 = g13 * i11;
        const float l41 = g14 * i11;

        const float d22 = g22 - l21 * l21;
        const float i22 = rsqrtf(d22);
        const float l32 = (g23 - l31 * l21) * i22;
        const float l42 = (g24 - l41 * l21) * i22;

        const float d33 = g33 - l31 * l31 - l32 * l32;
        const float i33 = rsqrtf(d33);
        const float l43 = (g34 - l41 * l31 - l42 * l32) * i33;

        const float d44 = g44 - l41 * l41 - l42 * l42 - l43 * l43;
        const float i44 = rsqrtf(d44);

        // Forward solve L y = b
        const float y1 = b1 * i11;
        const float y2 = (b2 - l21 * y1) * i22;
        const float y3 = (b3 - l31 * y1 - l32 * y2) * i33;
        const float y4 = (b4 - l41 * y1 - l42 * y2 - l43 * y3) * i44;

        // Back solve L^T w = y
        const float w4 = y4 * i44;
        const float w3 = (y3 - l43 * w4) * i33;
        const float w2 = (y2 - l32 * w3 - l42 * w4) * i22;
        const float w1 = (y1 - l21 * w2 - l31 * w3 - l41 * w4) * i11;

        out[batch] = make_float4(w1, w2, w3, w4);
    }
}

extern "C" void kernel_launch(void* const* d_in, const int* in_sizes, int n_in,
                              void* d_out, int out_size)
{
    const float* x = (const float*)d_in[0];       // (B, 32, 4) fp32
    float4* out = (float4*)d_out;                 // (B, 4) fp32
    const int B = in_sizes[0] / (32 * 4);         // 262144

    // 4 threads per batch, 256 threads per block -> 64 batches per block.
    // B*4 is an exact multiple of 256 (B = 262144), so the grid is exact.
    const int threads = 256;
    const int blocks = (B * 4) / threads;
    basic_ls_kernel<<<blocks, threads>>>(x, out);
}